// round 15
// baseline (speedup 1.0000x reference)
#include <cuda_runtime.h>
#include <cuda_fp16.h>
#include <math.h>

#define Qn 1024
#define Tn 256
#define Nn 100
#define Kn 300
#define KP 320          // padded K (5 chunks of 64)
#define EPSGAP 0.06f    // fp16 1-term ambiguity threshold (~5 sigma) for exact rescue

typedef unsigned long long u64;

__device__ float g_cls[Qn * 8];
__device__ float g_v2[Tn];
__device__ int   g_lab[Tn];
__device__ int   g_clo[Tn];
__device__ int   g_tperm[Tn];
__device__ __half g_pb[Qn * KP];             // pred fp16 plane, [q][KP]
__device__ unsigned g_sp[2 * Tn * 648];      // extended-target pair table (fp16x2)
__device__ float2 g_predT2[150 * Qn];        // transposed pred k-pairs [kp][q]
__device__ float g_pab[2 * Tn * Qn];         // per-(dir,t,q) best ab
__device__ int   g_pix[2 * Tn * Qn];         // its v index
__device__ float g_pv2[2 * Tn * Qn];         // runner-up ab
__device__ int   g_flist[Tn * Qn];           // flagged (t<<10|q)
__device__ int   g_fcnt;

__device__ __forceinline__ void ffma2(u64& c, u64 a, u64 b) {
    asm("fma.rn.f32x2 %0, %1, %2, %3;" : "=l"(c) : "l"(a), "l"(b), "l"(c));
}
__device__ __forceinline__ float pairsum(u64 v) {
    return __uint_as_float((unsigned)v) + __uint_as_float((unsigned)(v >> 32));
}
__device__ __forceinline__ unsigned smem_u32(const void* p) {
    unsigned a;
    asm("{ .reg .u64 t; cvta.to.shared.u64 t, %1; cvt.u32.u64 %0, t; }" : "=r"(a) : "l"(p));
    return a;
}
__device__ __forceinline__ void cp_async16(unsigned dst, const void* src) {
    asm volatile("cp.async.cg.shared.global [%0], [%1], 16;" :: "r"(dst), "l"(src) : "memory");
}
__device__ __forceinline__ void cp_commit() {
    asm volatile("cp.async.commit_group;" ::: "memory");
}
__device__ __forceinline__ void mma16816h(float* c, const unsigned* a, unsigned b0, unsigned b1) {
    asm volatile(
        "mma.sync.aligned.m16n8k16.row.col.f32.f16.f16.f32 "
        "{%0,%1,%2,%3}, {%4,%5,%6,%7}, {%8,%9}, {%0,%1,%2,%3};"
        : "+f"(c[0]), "+f"(c[1]), "+f"(c[2]), "+f"(c[3])
        : "r"(a[0]), "r"(a[1]), "r"(a[2]), "r"(a[3]), "r"(b0), "r"(b1));
}
__device__ __forceinline__ void top2_merge(float& v1, int& x1, float& v2,
                                           float ov1, int ox1, float ov2) {
    float lo = fminf(v1, ov1);
    if (ov1 > v1)               { v1 = ov1; x1 = ox1; }
    else if (ov1 == v1 && ox1 < x1) x1 = ox1;
    v2 = fmaxf(v2, fmaxf(lo, ov2));
}

// ---------------------------------------------------------------------------
__device__ __forceinline__ float sext_fwd(const float* __restrict__ tg, int idx) {
    int m = idx / 3, c = idx - m * 3;
    int mm = (m >= Nn) ? (m - Nn) : m;
    return tg[mm * 3 + c];
}
__device__ __forceinline__ float sext_bwd(const float* __restrict__ tg, int idx) {
    int m = idx / 3, c = idx - m * 3;
    int mm = (m >= Nn) ? (m - Nn) : m;
    return tg[(Nn - 1 - mm) * 3 + c];
}

// ---------------------------------------------------------------------------
// pre: blocks 0..3 softmax; 4..131 p2 (warp/q); 132..163 v2 (warp/t); 164 labels+perm
__global__ void pre_kernel(const float* __restrict__ pred,
                           const float* __restrict__ vlog,
                           const float* __restrict__ tlog,
                           const float* __restrict__ clog,
                           const float* __restrict__ tgt,
                           const int* __restrict__ lab32,
                           const int* __restrict__ clo32)
{
    const int tid = threadIdx.x;
    const int bx  = blockIdx.x;
    if (bx < 4) {
        const int q = bx * 256 + tid;
        float x0 = tlog[q*4+0], x1 = tlog[q*4+1], x2 = tlog[q*4+2], x3 = tlog[q*4+3];
        float m  = fmaxf(fmaxf(x0, x1), fmaxf(x2, x3));
        float e0 = expf(x0-m), e1 = expf(x1-m), e2 = expf(x2-m), e3 = expf(x3-m);
        float s  = e0 + e1 + e2 + e3;
        g_cls[q*8+0] = logf(e0/s + 1e-6f);
        g_cls[q*8+1] = logf(e1/s + 1e-6f);
        g_cls[q*8+2] = logf(e2/s + 1e-6f);
        g_cls[q*8+3] = logf(e3/s + 1e-6f);
        float a0 = vlog[q*2+0], a1 = vlog[q*2+1];
        float ma = fmaxf(a0, a1);
        float f0 = expf(a0-ma), f1 = expf(a1-ma);
        g_cls[q*8+4] = logf(f0/(f0+f1) + 1e-6f);
        float b0 = clog[q*2+0], b1 = clog[q*2+1];
        float mb = fmaxf(b0, b1);
        float h0 = expf(b0-mb), h1 = expf(b1-mb);
        float hs = h0 + h1;
        g_cls[q*8+5] = logf(h0/hs + 1e-6f);
        g_cls[q*8+6] = logf(h1/hs + 1e-6f);
    } else if (bx < 132) {
        const int q    = (bx - 4) * 8 + (tid >> 5);
        const int lane = tid & 31;
        const float* p = pred + q * Kn;
        float s = 0.f;
        #pragma unroll
        for (int j = 0; j < 10; j++) {
            int k = lane + 32 * j;
            if (k < Kn) { float v = p[k]; s = fmaf(v, v, s); }
        }
        #pragma unroll
        for (int m = 16; m >= 1; m >>= 1) s += __shfl_xor_sync(0xffffffffu, s, m);
        if (lane == 0) g_cls[q*8+7] = s;
    } else if (bx < 164) {
        const int t    = (bx - 132) * 8 + (tid >> 5);
        const int lane = tid & 31;
        const float* p = tgt + t * Kn;
        float s = 0.f;
        #pragma unroll
        for (int j = 0; j < 10; j++) {
            int k = lane + 32 * j;
            if (k < Kn) { float v = p[k]; s = fmaf(v, v, s); }
        }
        #pragma unroll
        for (int m = 16; m >= 1; m >>= 1) s += __shfl_xor_sync(0xffffffffu, s, m);
        if (lane == 0) g_v2[t] = s;
    } else {
        if (tid == 0) g_fcnt = 0;   // reset rescue list each launch (graph replays)
        __shared__ int flag;
        if (tid == 0) flag = 0;
        __syncthreads();
        if (tid < 128) {
            if (lab32[2*tid+1] != 0 || clo32[2*tid+1] != 0) atomicOr(&flag, 1);
        }
        __syncthreads();
        const int t = tid;
        int lv, cv;
        if (flag) { lv = lab32[t]; cv = clo32[t]; }
        else {
            lv = (int)((const long long*)lab32)[t];
            cv = (int)((const long long*)clo32)[t];
        }
        g_lab[t] = lv;
        g_clo[t] = cv;
        __syncthreads();
        if (tid == 0) {
            int a = 0, b = 0;
            for (int i = 0; i < Tn; i++) if (g_clo[i]) g_tperm[a++] = i;
            for (int i = 0; i < Tn; i++) if (!g_clo[i]) g_tperm[a + (b++)] = i;
        }
    }
}

// fp16 plane for preds, fp16 target pair tables, pred k-pair transpose
__global__ void pre2_kernel(const float* __restrict__ pred,
                            const float* __restrict__ tgt)
{
    int idx = blockIdx.x * 256 + threadIdx.x;
    if (blockIdx.x < 1280) {
        int q = idx / KP, k = idx - q * KP;
        float x = (k < Kn) ? pred[q * Kn + k] : 0.f;
        g_pb[idx] = __float2half_rn(x);
    } else if (blockIdx.x < 2576) {
        int i2 = idx - 1280 * 256;
        if (i2 >= 2 * Tn * 648) return;
        int dt = i2 / 648, j = i2 - dt * 648;
        int dir = dt >> 8, t = dt & 255;
        const float* tg = tgt + t * Kn;
        float x0 = 0.f, x1 = 0.f;
        if (j < 600)     x0 = dir ? sext_bwd(tg, j)     : sext_fwd(tg, j);
        if (j + 1 < 600) x1 = dir ? sext_bwd(tg, j + 1) : sext_fwd(tg, j + 1);
        __half h0 = __float2half_rn(x0), h1 = __float2half_rn(x1);
        g_sp[i2] = (unsigned)__half_as_ushort(h0) | ((unsigned)__half_as_ushort(h1) << 16);
    } else {
        int i3 = idx - 2576 * 256;           // 0 .. 153599
        if (i3 >= 150 * Qn) return;
        int q = i3 / 150, kp = i3 - q * 150;
        const float2 v = *(const float2*)(pred + q * Kn + 2 * kp);
        g_predT2[kp * Qn + q] = v;
    }
}

// ---------------------------------------------------------------------------
__device__ __forceinline__ void epilogue_write(
    float best_ab, int ids, int t, int q, int clos,
    const float* __restrict__ clw, float* __restrict__ out, int write_ids)
{
    const float p2 = g_cls[q*8+7];
    float d2 = fmaxf(g_v2[t] + p2 - 2.0f * best_ab, 0.0f) / 100.0f;
    const int lab = g_lab[t];
    float cls = g_cls[q*8+lab] + g_cls[q*8+4] + g_cls[q*8+5+clos];
    float C = d2 * clw[t] - cls;
    out[q * Tn + t] = C;
    if (write_ids) out[Qn * Tn + q * Tn + t] = (float)ids;
}

// ---------------------------------------------------------------------------
// HMMA kernel: one CTA = (closed t, dir, 128-q tile). 8 warps = 4(M) x 2(N).
// fp16 1-term: D = Ah*B. B staged via cp.async double buffer.
#define BPITCH 144
__global__ void __launch_bounds__(256, 2)
mma_kernel(int write_ids)
{
    __shared__ unsigned ssp[648];
    __shared__ char sB[2][128 * BPITCH];
    __shared__ float redv[4][128];
    __shared__ int   redi[4][128];
    __shared__ float redv2[4][128];

    const int tid  = threadIdx.x;
    const int wid  = tid >> 5, lane = tid & 31;
    const int wm   = wid & 3,  wn = wid >> 2;
    const int t    = g_tperm[blockIdx.x];
    if (!g_clo[t]) return;
    const int dir  = blockIdx.y >> 3;
    const int q0   = (blockIdx.y & 7) * 128;
    const int m0   = wm * 32;
    const int n0   = wn * 64;
    const int g    = lane >> 2;
    const int t2   = (lane & 3) * 2;

    // cp.async staging geometry: 1024 16B-chunks per kc, 4 per thread
    const int srow = tid >> 1;              // 0..127 (two threads per row)
    const int scol = (tid & 1) * 4;         // chunk base within row: 0 or 4
    unsigned sBu[2];
    sBu[0] = smem_u32(&sB[0][0]);
    sBu[1] = smem_u32(&sB[1][0]);
    const __half* gsrc = g_pb + (u64)(q0 + srow) * KP;

    {
        const unsigned* gh = g_sp + (dir * Tn + t) * 648;
        for (int j = tid; j < 648; j += 256) ssp[j] = gh[j];
    }

    // prologue: stage kc=0 into buffer 0
    #pragma unroll
    for (int w2 = 0; w2 < 4; w2++)
        cp_async16(sBu[0] + srow * BPITCH + (scol + w2) * 16, gsrc + (scol + w2) * 8);
    cp_commit();

    float c[2][8][4];
    #pragma unroll
    for (int mt = 0; mt < 2; mt++)
        #pragma unroll
        for (int nt = 0; nt < 8; nt++)
            #pragma unroll
            for (int r = 0; r < 4; r++) c[mt][nt][r] = 0.f;

    int off0[2], off1[2];
    bool val0[2], val1[2], tilev[2];
    #pragma unroll
    for (int mt = 0; mt < 2; mt++) {
        int v0 = m0 + mt * 16 + g;
        val0[mt]  = (v0 < 100);
        val1[mt]  = (v0 + 8 < 100);
        tilev[mt] = (m0 + mt * 16 < 100);
        off0[mt]  = val0[mt] ? 3 * (100 - v0) : 0;
        off1[mt]  = val1[mt] ? 3 * (100 - v0) - 24 : 0;
    }

    for (int kc = 0; kc < 5; kc++) {
        const int buf = kc & 1;
        __syncthreads();   // everyone done reading buf^1 (from kc-1) before overwrite
        if (kc < 4) {
            const __half* s2 = gsrc + (kc + 1) * 64;
            #pragma unroll
            for (int w2 = 0; w2 < 4; w2++)
                cp_async16(sBu[buf ^ 1] + srow * BPITCH + (scol + w2) * 16, s2 + (scol + w2) * 8);
            cp_commit();
            asm volatile("cp.async.wait_group 1;" ::: "memory");
        } else {
            asm volatile("cp.async.wait_group 0;" ::: "memory");
        }
        __syncthreads();   // buf fully landed for all threads

        #pragma unroll
        for (int ks = 0; ks < 4; ks++) {
            const int kk = kc * 64 + ks * 16 + t2;
            unsigned ah[2][4];
            #pragma unroll
            for (int mt = 0; mt < 2; mt++) {
                ah[mt][0] = val0[mt] ? ssp[off0[mt] + kk]     : 0u;
                ah[mt][1] = val1[mt] ? ssp[off1[mt] + kk]     : 0u;
                ah[mt][2] = val0[mt] ? ssp[off0[mt] + kk + 8] : 0u;
                ah[mt][3] = val1[mt] ? ssp[off1[mt] + kk + 8] : 0u;
            }
            #pragma unroll
            for (int nt = 0; nt < 8; nt++) {
                const int brow = n0 + nt * 8 + g;
                const char* bp = sB[buf] + brow * BPITCH + (ks * 16 + t2) * 2;
                unsigned b0 = *(const unsigned*)bp;
                unsigned b1 = *(const unsigned*)(bp + 16);
                #pragma unroll
                for (int mt = 0; mt < 2; mt++)
                    if (tilev[mt]) mma16816h(c[mt][nt], ah[mt], b0, b1);
            }
        }
    }

    // ---- epilogue: top-2 argmax over v per q column ----
    const float NINF = -__int_as_float(0x7f800000);
    #pragma unroll
    for (int nt = 0; nt < 8; nt++) {
        #pragma unroll
        for (int cp = 0; cp < 2; cp++) {
            float bv = NINF; int bx = 127; float bv2 = NINF;
            #pragma unroll
            for (int mt = 0; mt < 2; mt++) {
                #pragma unroll
                for (int rh = 0; rh < 2; rh++) {
                    int v = m0 + mt * 16 + rh * 8 + g;
                    float val = (v < 100) ? c[mt][nt][rh * 2 + cp] : NINF;
                    top2_merge(bv, bx, bv2, val, v, NINF);
                }
            }
            #pragma unroll
            for (int m = 4; m <= 16; m <<= 1) {
                float ov  = __shfl_xor_sync(0xffffffffu, bv, m);
                int   ox  = __shfl_xor_sync(0xffffffffu, bx, m);
                float ov2 = __shfl_xor_sync(0xffffffffu, bv2, m);
                top2_merge(bv, bx, bv2, ov, ox, ov2);
            }
            if (lane < 4) {
                int col = n0 + nt * 8 + t2 + cp;
                redv[wm][col]  = bv;
                redi[wm][col]  = bx;
                redv2[wm][col] = bv2;
            }
        }
    }
    __syncthreads();
    if (tid < 128) {
        int col = tid;
        float bv = redv[0][col]; int bx = redi[0][col]; float bv2 = redv2[0][col];
        #pragma unroll
        for (int w = 1; w < 4; w++)
            top2_merge(bv, bx, bv2, redv[w][col], redi[w][col], redv2[w][col]);
        int o = (dir * Tn + t) * Qn + q0 + col;
        g_pab[o] = bv; g_pix[o] = bx; g_pv2[o] = bv2;
    }
}

// ---------------------------------------------------------------------------
__global__ void combine_kernel(const float* __restrict__ clw,
                               float* __restrict__ out, int write_ids)
{
    int idx = blockIdx.x * 256 + threadIdx.x;
    int t = idx >> 10, q = idx & 1023;
    if (!g_clo[t]) return;
    float f1 = g_pab[t * Qn + q];        int xf = g_pix[t * Qn + q];
    float f2 = g_pv2[t * Qn + q];
    float w1 = g_pab[(Tn + t) * Qn + q]; int xb = g_pix[(Tn + t) * Qn + q];
    float w2 = g_pv2[(Tn + t) * Qn + q];
    float best, second; int ids;
    if (w1 > f1) { best = w1; ids = 99 - xb; second = fmaxf(f1, w2); }
    else         { best = f1; ids = xf;      second = fmaxf(w1, f2); }
    epilogue_write(best, ids, t, q, 1, clw, out, write_ids);
    if (best - second < EPSGAP) {
        int slot = atomicAdd(&g_fcnt, 1);
        g_flist[slot] = (t << 10) | q;
    }
}

// ---------------------------------------------------------------------------
// exact fp32 rescue: one warp per ambiguous (t,q), all 200 variants
__global__ void __launch_bounds__(256)
rescue_kernel(const float* __restrict__ pred, const float* __restrict__ tgt,
              const float* __restrict__ clw, float* __restrict__ out, int write_ids)
{
    const int lane = threadIdx.x & 31;
    const int gw   = (blockIdx.x * 256 + threadIdx.x) >> 5;
    const int nw   = gridDim.x * 8;
    const int n    = g_fcnt;
    const float NINF = -__int_as_float(0x7f800000);
    for (int i = gw; i < n; i += nw) {
        int code = g_flist[i];
        int t = code >> 10, q = code & 1023;
        const float* tg = tgt + t * Kn;
        const float* pq = pred + q * Kn;
        float bv = NINF; int bx = 255;
        for (int r = lane; r < 200; r += 32) {
            int  sh  = (r < 100) ? (100 - r) : (200 - r);
            bool rev = (r >= 100);
            float c0 = 0.f, c1 = 0.f, c2 = 0.f;
            for (int j = 0; j < 100; j++) {
                int jj = j + sh; if (jj >= 100) jj -= 100;
                int row = rev ? (99 - jj) : jj;
                c0 = fmaf(pq[j*3+0], tg[row*3+0], c0);
                c1 = fmaf(pq[j*3+1], tg[row*3+1], c1);
                c2 = fmaf(pq[j*3+2], tg[row*3+2], c2);
            }
            float ab = c0 + c1 + c2;
            if (ab > bv) { bv = ab; bx = r; }
        }
        #pragma unroll
        for (int m = 16; m >= 1; m >>= 1) {
            float ov = __shfl_xor_sync(0xffffffffu, bv, m);
            int   ox = __shfl_xor_sync(0xffffffffu, bx, m);
            if (ov > bv || (ov == bv && ox < bx)) { bv = ov; bx = ox; }
        }
        if (lane == 0) {
            int ids = (bx < 100) ? bx : 199 - bx;
            epilogue_write(bv, ids, t, q, 1, clw, out, write_ids);
        }
    }
}

// ---------------------------------------------------------------------------
// open curves: k-pair transposed loads (LDG.64, batched MLP=6), ffma2 math
__global__ void __launch_bounds__(256, 4)
light_kernel(const float* __restrict__ tgt,
             const float* __restrict__ clw, float* __restrict__ out, int write_ids)
{
    __shared__ float2 sfp[152], sbp[152];
    const int t = blockIdx.x;
    if (g_clo[t]) return;
    const int q = blockIdx.y * 256 + threadIdx.x;
    const float* tg = tgt + t * Kn;
    for (int j = threadIdx.x; j < 150; j += 256) {
        int idx = 300 + 2 * j;
        sfp[j] = make_float2(sext_fwd(tg, idx), sext_fwd(tg, idx + 1));
        sbp[j] = make_float2(sext_bwd(tg, idx), sext_bwd(tg, idx + 1));
    }
    __syncthreads();
    const u64* p2  = (const u64*)g_predT2;
    const u64* suf = (const u64*)sfp;
    const u64* sub = (const u64*)sbp;
    u64 af0 = 0ull, af1 = 0ull, ab0 = 0ull, ab1 = 0ull;
    #pragma unroll 1
    for (int i0 = 0; i0 < 150; i0 += 6) {
        u64 p[6];
        #pragma unroll
        for (int j = 0; j < 6; j++)
            p[j] = p2[(i0 + j) * Qn + q];
        #pragma unroll
        for (int j = 0; j < 6; j++) {
            if (j & 1) { ffma2(af1, p[j], suf[i0 + j]); ffma2(ab1, p[j], sub[i0 + j]); }
            else       { ffma2(af0, p[j], suf[i0 + j]); ffma2(ab0, p[j], sub[i0 + j]); }
        }
    }
    float af = pairsum(af0) + pairsum(af1);
    float ab = pairsum(ab0) + pairsum(ab1);
    epilogue_write(fmaxf(af, ab), 0, t, q, 0, clw, out, write_ids);
}

// ---------------------------------------------------------------------------
extern "C" void kernel_launch(void* const* d_in, const int* in_sizes, int n_in,
                              void* d_out, int out_size)
{
    const float* pred = (const float*)d_in[0];
    const float* vlog = (const float*)d_in[1];
    const float* tlog = (const float*)d_in[2];
    const float* clog = (const float*)d_in[3];
    const float* tgt  = (const float*)d_in[4];
    const int*   lab  = (const int*)d_in[5];
    const int*   clo  = (const int*)d_in[6];
    const float* clw  = (const float*)d_in[7];
    float* out = (float*)d_out;

    const int write_ids = (out_size >= 2 * Qn * Tn) ? 1 : 0;

    pre_kernel<<<165, 256>>>(pred, vlog, tlog, clog, tgt, lab, clo);
    pre2_kernel<<<2576 + 600, 256>>>(pred, tgt);
    mma_kernel<<<dim3(Tn, 16), 256>>>(write_ids);
    light_kernel<<<dim3(Tn, 4), 256>>>(tgt, clw, out, write_ids);
    combine_kernel<<<1024, 256>>>(clw, out, write_ids);
    rescue_kernel<<<512, 256>>>(pred, tgt, clw, out, write_ids);
}